// round 2
// baseline (speedup 1.0000x reference)
#include <cuda_runtime.h>

// Mann eddy-lifetime model:
//   t2 = (L*|k|)^2
//   w  = 1/(1+t2)
//   s  = 2F1(1/3, -3/2, 4/3, w)   (fixed polynomial, Pfaff-transformed series)
//   tau = rsqrt(t2 * w^{1/3} * s)        [== t^{-2/3} / sqrt((t2*w)^{1/3} * s)]
//   out = gamma * tau   (0 where t2 == 0)

constexpr int NDEG = 24;

struct PolyCoeffs { float c[NDEG + 1]; };

__host__ __device__ constexpr PolyCoeffs make_coeffs() {
    PolyCoeffs p{};
    double term = 1.0;
    p.c[0] = 1.0f;
    for (int n = 0; n < NDEG; ++n) {
        // a = 1/3, bp = c - b = -3/2, c = 4/3
        term *= ((1.0 / 3.0 + n) * (n - 1.5)) / ((4.0 / 3.0 + n) * (n + 1.0));
        p.c[n + 1] = (float)term;
    }
    return p;
}

__device__ __forceinline__ float mann_series(float w) {
    constexpr PolyCoeffs P = make_coeffs();
    float s = P.c[NDEG];
#pragma unroll
    for (int n = NDEG - 1; n >= 0; --n)
        s = fmaf(s, w, P.c[n]);
    return s;
}

__device__ __forceinline__ float mann_tau(float t2) {
    float w = __fdividef(1.0f, 1.0f + t2);
    float s = mann_series(w);
    float cw = exp2f(0.3333333433f * __log2f(w));  // w^{1/3}, == 1 at w=1
    float r = rsqrtf(t2 * cw * s);
    return (t2 > 0.0f) ? r : 0.0f;
}

__global__ void __launch_bounds__(256)
mann_kernel4(const float4* __restrict__ k4,
             const float* __restrict__ Lp,
             const float* __restrict__ gp,
             float4* __restrict__ out,
             int n4) {
    int i = blockIdx.x * blockDim.x + threadIdx.x;
    if (i >= n4) return;

    float L = __ldg(Lp);
    float g = __ldg(gp);
    float L2 = L * L;

    float4 a = k4[3 * i + 0];
    float4 b = k4[3 * i + 1];
    float4 c = k4[3 * i + 2];

    float t0 = L2 * fmaf(a.x, a.x, fmaf(a.y, a.y, a.z * a.z));
    float t1 = L2 * fmaf(a.w, a.w, fmaf(b.x, b.x, b.y * b.y));
    float t2 = L2 * fmaf(b.z, b.z, fmaf(b.w, b.w, c.x * c.x));
    float t3 = L2 * fmaf(c.y, c.y, fmaf(c.z, c.z, c.w * c.w));

    float4 o;
    o.x = g * mann_tau(t0);
    o.y = g * mann_tau(t1);
    o.z = g * mann_tau(t2);
    o.w = g * mann_tau(t3);
    out[i] = o;
}

__global__ void mann_kernel1(const float* __restrict__ k,
                             const float* __restrict__ Lp,
                             const float* __restrict__ gp,
                             float* __restrict__ out,
                             int start, int n) {
    int i = start + blockIdx.x * blockDim.x + threadIdx.x;
    if (i >= n) return;
    float L = __ldg(Lp);
    float g = __ldg(gp);
    float x = k[3 * i + 0], y = k[3 * i + 1], z = k[3 * i + 2];
    float t2 = (L * L) * fmaf(x, x, fmaf(y, y, z * z));
    out[i] = g * mann_tau(t2);
}

extern "C" void kernel_launch(void* const* d_in, const int* in_sizes, int n_in,
                              void* d_out, int out_size) {
    const float* k = (const float*)d_in[0];
    const float* L = (const float*)d_in[1];
    const float* g = (const float*)d_in[2];
    float* out = (float*)d_out;

    int n4 = out_size >> 2;
    if (n4 > 0) {
        int blocks = (n4 + 255) / 256;
        mann_kernel4<<<blocks, 256>>>((const float4*)k, L, g, (float4*)out, n4);
    }
    int rem = out_size - (n4 << 2);
    if (rem > 0) {
        mann_kernel1<<<(rem + 127) / 128, 128>>>(k, L, g, out, n4 << 2, out_size);
    }
}